// round 5
// baseline (speedup 1.0000x reference)
#include <cuda_runtime.h>

#define NT 256
#define NB 1036
#define NBINS 10
#define FULLMASK 0xffffffffu

// pass1: rows 0..9 = exact conf chunk sums, 10..19 = counts, 20..29 = corrects
__device__ float g_scratch[32 * NB];
__device__ float g_prefix[NB * NBINS];   // exclusive per-bin prefix of conf chunk sums
__device__ float g_d[NBINS * NB];        // pass2 emulated (lossy) conf chunk sums

__device__ __forceinline__ int bin_of(float x) {
    return min(__float2int_rz(x * 10.0f), 9);
}

__device__ __forceinline__ void process_row(const float r[10], int lab,
                                            const float* __restrict__ rowp,
                                            int tid,
                                            float2 (*s_cc)[NT],
                                            int (*s_cor)[NT]) {
    float m = r[0];
#pragma unroll
    for (int j = 1; j < 10; j++) m = fmaxf(m, r[j]);

#pragma unroll
    for (int j = 0; j < 10; j++) {
        float x = r[j];
        int b = bin_of(x);
        float2 v = s_cc[b][tid];
        v.x += x;            // exact chunk conf sum (feeds prefix)
        v.y += 1.0f;         // count
        s_cc[b][tid] = v;
    }
    float xl = __ldg(rowp + lab);   // L1 hit reload of the true-class prob
    if (xl == m) s_cor[bin_of(xl)][tid]++;
}

// ---------------- pass 1: counts, corrects, exact conf chunk sums ----------------
__global__ __launch_bounds__(NT) void ece_pass1(const float* __restrict__ probs,
                                                const int* __restrict__ labels,
                                                int n) {
    __shared__ float2 s_cc[NBINS][NT];
    __shared__ int    s_cor[NBINS][NT];
    __shared__ float  s_red[240];
    const int tid = threadIdx.x;
#pragma unroll
    for (int b = 0; b < NBINS; b++) {
        s_cc[b][tid] = make_float2(0.0f, 0.0f);
        s_cor[b][tid] = 0;
    }

    const int npairs = n >> 1;
    const int ppb = (npairs + NB - 1) / NB;          // pairs per contiguous slab
    const int p0  = blockIdx.x * ppb;
    const int p1  = min(p0 + ppb, npairs);

    const float4* __restrict__ p4 = (const float4*)probs;
    const int2* __restrict__ lab2 = (const int2*)labels;

    for (int p = p0 + tid; p < p1; p += NT) {
        const float4 v0 = p4[5 * p + 0];
        const float4 v1 = p4[5 * p + 1];
        const float4 v2 = p4[5 * p + 2];
        const float4 v3 = p4[5 * p + 3];
        const float4 v4 = p4[5 * p + 4];
        const int2 lb = lab2[p];
        const float r0[10] = {v0.x, v0.y, v0.z, v0.w, v1.x,
                              v1.y, v1.z, v1.w, v2.x, v2.y};
        const float r1[10] = {v2.z, v2.w, v3.x, v3.y, v3.z,
                              v3.w, v4.x, v4.y, v4.z, v4.w};
        const float* rowp = probs + 20 * p;
        process_row(r0, lb.x, rowp,      tid, s_cc, s_cor);
        process_row(r1, lb.y, rowp + 10, tid, s_cc, s_cor);
    }
    if (blockIdx.x == NB - 1 && tid == 0 && (n & 1)) {
        const int row = n - 1;
        float r[10];
#pragma unroll
        for (int j = 0; j < 10; j++) r[j] = probs[row * 10 + j];
        process_row(r, labels[row], probs + row * 10, tid, s_cc, s_cor);
    }

    __syncthreads();
    if (tid < 240) {
        const int row = tid >> 3, c = tid & 7, base = c * 32;
        float part = 0.0f;
        if (row < 10) {
#pragma unroll
            for (int k = 0; k < 32; k++) part += s_cc[row][base + k].x;
        } else if (row < 20) {
#pragma unroll
            for (int k = 0; k < 32; k++) part += s_cc[row - 10][base + k].y;
        } else {
#pragma unroll
            for (int k = 0; k < 32; k++) part += (float)s_cor[row - 20][base + k];
        }
        s_red[tid] = part;
    }
    __syncthreads();
    if (tid < 30) {
        float t = 0.0f;
#pragma unroll
        for (int c = 0; c < 8; c++) t += s_red[tid * 8 + c];
        g_scratch[tid * NB + blockIdx.x] = t;
    }
}

// ---------------- scan: exclusive per-bin prefix over slab conf sums ----------------
__global__ void ece_scan() {
    const int w = threadIdx.x >> 5;   // bin
    const int l = threadIdx.x & 31;
    if (w >= NBINS) return;
    float carry = 0.0f;
    for (int base = 0; base < NB; base += 32) {
        const int idx = base + l;
        float incl = (idx < NB) ? g_scratch[w * NB + idx] : 0.0f;
#pragma unroll
        for (int o = 1; o < 32; o <<= 1) {
            float t = __shfl_up_sync(FULLMASK, incl, o);
            if (l >= o) incl += t;
        }
        float excl = __shfl_up_sync(FULLMASK, incl, 1);
        if (l == 0) excl = 0.0f;
        if (idx < NB) g_prefix[idx * NBINS + w] = carry + excl;
        carry += __shfl_sync(FULLMASK, incl, 31);
    }
}

// ---------------- pass 2: emulate single-fp32-accumulator conf sums ----------------
__global__ __launch_bounds__(NT) void ece_pass2(const float* __restrict__ probs, int n) {
    __shared__ float s_d[NBINS][NT];
    __shared__ float s_A[NBINS];
    __shared__ float s_red[80];
    const int tid = threadIdx.x;
#pragma unroll
    for (int b = 0; b < NBINS; b++) s_d[b][tid] = 0.0f;
    if (tid < NBINS) s_A[tid] = g_prefix[blockIdx.x * NBINS + tid];
    __syncthreads();

    const int npairs = n >> 1;
    const int ppb = (npairs + NB - 1) / NB;
    const int p0  = blockIdx.x * ppb;
    const int p1  = min(p0 + ppb, npairs);
    const float4* __restrict__ p4 = (const float4*)probs;

    for (int p = p0 + tid; p < p1; p += NT) {
        const float4 v0 = p4[5 * p + 0];
        const float4 v1 = p4[5 * p + 1];
        const float4 v2 = p4[5 * p + 2];
        const float4 v3 = p4[5 * p + 3];
        const float4 v4 = p4[5 * p + 4];
        const float r[20] = {v0.x, v0.y, v0.z, v0.w, v1.x, v1.y, v1.z, v1.w,
                             v2.x, v2.y, v2.z, v2.w, v3.x, v3.y, v3.z, v3.w,
                             v4.x, v4.y, v4.z, v4.w};
#pragma unroll
        for (int j = 0; j < 20; j++) {
            const float x = r[j];
            const int b = bin_of(x);
            const float A = s_A[b];
            const float t = A + x;      // fp32 add against large accumulator
            const float d = t - A;      // effective amount actually absorbed
            s_d[b][tid] += d;
        }
    }
    if (blockIdx.x == NB - 1 && tid == 0 && (n & 1)) {
        const int row = n - 1;
#pragma unroll
        for (int j = 0; j < 10; j++) {
            const float x = probs[row * 10 + j];
            const int b = bin_of(x);
            const float A = s_A[b];
            const float t = A + x;
            s_d[b][tid] += (t - A);
        }
    }

    __syncthreads();
    if (tid < 80) {
        const int row = tid >> 3, c = tid & 7, base = c * 32;
        float part = 0.0f;
#pragma unroll
        for (int k = 0; k < 32; k++) part += s_d[row][base + k];
        s_red[tid] = part;
    }
    __syncthreads();
    if (tid < 10) {
        float t = 0.0f;
#pragma unroll
        for (int c = 0; c < 8; c++) t += s_red[tid * 8 + c];
        g_d[tid * NB + blockIdx.x] = t;
    }
}

// ---------------- final ----------------
__global__ __launch_bounds__(1024) void ece_final(float* __restrict__ out) {
    __shared__ float tot[32];
    const int tid = threadIdx.x;
    const int row = tid >> 5;
    const int c   = tid & 31;

    float s = 0.0f;
    if (row < 10) {
        for (int b = c; b < NB; b += 32) s += g_d[row * NB + b];            // lossy conf sums
    } else if (row < 30) {
        for (int b = c; b < NB; b += 32) s += g_scratch[row * NB + b];      // counts / corrects
    }
#pragma unroll
    for (int o = 16; o > 0; o >>= 1) s += __shfl_down_sync(FULLMASK, s, o);
    if (c == 0) tot[row] = s;
    __syncthreads();

    if (tid == 0) {
        float total = 0.0f;
#pragma unroll
        for (int b = 0; b < 10; b++) total += tot[10 + b];
        float ece = 0.0f;
#pragma unroll
        for (int b = 0; b < 10; b++) {
            const float cnt  = tot[10 + b];
            const float conf = tot[b]      / cnt;
            const float acc  = tot[20 + b] / cnt;
            ece += fabsf(conf - acc) * cnt;
            out[1 + b]  = (float)((double)(b + 1) * 0.1) - 0.05f;
            out[11 + b] = acc;
        }
        out[0] = ece / total;
    }
}

extern "C" void kernel_launch(void* const* d_in, const int* in_sizes, int n_in,
                              void* d_out, int out_size) {
    const float* probs  = (const float*)d_in[0];
    const int*   labels = (const int*)d_in[1];
    const int n = in_sizes[1];

    ece_pass1<<<NB, NT>>>(probs, labels, n);
    ece_scan<<<1, 320>>>();
    ece_pass2<<<NB, NT>>>(probs, n);
    ece_final<<<1, 1024>>>((float*)d_out);
}